// round 3
// baseline (speedup 1.0000x reference)
#include <cuda_runtime.h>
#include <math.h>

#define MDIM 128        // N_COMBOS (dual dim)
#define NDIM 512        // N_STRUCTS (primal dim)
#define HID  20
#define NITER 60
#define CONTROLF 10.0f
#define RCAP 64         // max nnz per row of S (mean ~16)
#define CCAP 24         // max nnz per col of S (mean ~4)
#define RROWS 4         // batch rows per CTA

// Scratch (no allocations allowed). idxT arrays are transposed [j][owner] so
// per-iteration index loads are coalesced. _bld are unsorted build buffers;
// final arrays are bank-schedule-sorted (see prep_kernel).
__device__ int            g_csr_cnt[MDIM];
__device__ unsigned short g_csr_bld[RCAP * MDIM];
__device__ unsigned short g_csr_idxT[RCAP * MDIM];   // [j][m], sorted by ((n-m)&7)
__device__ int            g_csc_cnt[NDIM];
__device__ unsigned char  g_csc_bld[CCAP * NDIM];
__device__ unsigned char  g_csc_idxT[CCAP * NDIM];   // [j][n], sorted by ((m-n)&7)
__device__ float          g_tau;

// ---------------------------------------------------------------------------
// Kernel 0 (1 block, 512 threads): build CSR (ballot, coalesced) + CSC
// (thread-per-column, coalesced), bank-schedule sort both, then 30-step power
// iteration for L = sqrt(lambda_max(S^T S + I)); tau = sig = 0.9/L.
// ---------------------------------------------------------------------------
__global__ void prep_kernel(const float* __restrict__ S) {
    const int t    = threadIdx.x;   // 0..511
    const int lane = t & 31;
    const int w    = t >> 5;        // warp 0..15

    // ---- CSC build: thread t scans column t (coalesced across threads) ----
    {
        int cnt = 0;
        for (int m = 0; m < MDIM; m++) {
            if (S[m * NDIM + t] != 0.0f) {
                if (cnt < CCAP) g_csc_bld[cnt * NDIM + t] = (unsigned char)m;
                cnt++;
            }
        }
        g_csc_cnt[t] = cnt < CCAP ? cnt : CCAP;
    }

    // ---- CSR build via ballot: warp w handles rows 8w..8w+7 (coalesced) ----
    for (int r = 0; r < 8; r++) {
        const int m = w * 8 + r;
        int c = 0;
        for (int j = 0; j < NDIM / 32; j++) {
            const int n = lane + 32 * j;
            const bool nz = (S[m * NDIM + n] != 0.0f);
            const unsigned mask = __ballot_sync(0xffffffffu, nz);
            if (nz) {
                const int pos = c + __popc(mask & ((1u << lane) - 1u));
                if (pos < RCAP) g_csr_bld[pos * MDIM + m] = (unsigned short)n;
            }
            c += __popc(mask);
        }
        if (lane == 0) g_csr_cnt[m] = c < RCAP ? c : RCAP;
    }
    __syncthreads();

    // ---- Bank-schedule sort (counting sort by key, 8 buckets) ----
    // CSR row m: key = ((n - m) & 7). At gather step j, lanes (consecutive m)
    // then hit bank groups ~(key_j + m) & 7 -> round-robin, minimal conflicts.
    if (t < MDIM) {
        const int cnt = g_csr_cnt[t];
        int cntk[8] = {0,0,0,0,0,0,0,0};
        for (int j = 0; j < cnt; j++) {
            const int n = g_csr_bld[j * MDIM + t];
            cntk[(n - t) & 7]++;
        }
        int off[8]; int s = 0;
        #pragma unroll
        for (int k = 0; k < 8; k++) { off[k] = s; s += cntk[k]; }
        for (int j = 0; j < cnt; j++) {
            const int n = g_csr_bld[j * MDIM + t];
            g_csr_idxT[(off[(n - t) & 7]++) * MDIM + t] = (unsigned short)n;
        }
    }
    // CSC col n: key = ((m - n) & 7)
    {
        const int cnt = g_csc_cnt[t];
        int cntk[8] = {0,0,0,0,0,0,0,0};
        for (int j = 0; j < cnt; j++) {
            const int m = g_csc_bld[j * NDIM + t];
            cntk[(m - t) & 7]++;
        }
        int off[8]; int s = 0;
        #pragma unroll
        for (int k = 0; k < 8; k++) { off[k] = s; s += cntk[k]; }
        for (int j = 0; j < cnt; j++) {
            const int m = g_csc_bld[j * NDIM + t];
            g_csc_idxT[(off[(m - t) & 7]++) * NDIM + t] = (unsigned char)m;
        }
    }
    __syncthreads();

    // ---- Power iteration ----
    __shared__ float v[NDIM];
    __shared__ float p[MDIM];
    __shared__ float red[16];

    v[t] = 1.0f;
    __syncthreads();

    const int ccnt = g_csc_cnt[t];
    float Lsq = 0.0f;

    for (int it = 0; it <= 30; it++) {
        if (t < MDIM) {
            float a = 0.0f;
            const int rc = g_csr_cnt[t];
            for (int j = 0; j < rc; j++) a += v[g_csr_idxT[j * MDIM + t]];
            p[t] = a;
        }
        __syncthreads();
        float a = v[t];
        for (int j = 0; j < ccnt; j++) a += p[g_csc_idxT[j * NDIM + t]];

        float s = (it == 30) ? (a * v[t]) : (a * a);
        #pragma unroll
        for (int o = 16; o > 0; o >>= 1) s += __shfl_xor_sync(0xffffffffu, s, o);
        if ((t & 31) == 0) red[t >> 5] = s;
        __syncthreads();
        float tot = 0.0f;
        #pragma unroll
        for (int ww = 0; ww < 16; ww++) tot += red[ww];

        if (it == 30) { Lsq = tot; break; }
        v[t] = a / sqrtf(tot);
        __syncthreads();
    }

    if (t == 0) g_tau = 0.9f / sqrtf(Lsq);
}

__device__ __forceinline__ float4 f4add(float4 a, float4 b) {
    return make_float4(a.x + b.x, a.y + b.y, a.z + b.z, a.w + b.w);
}

// ---------------------------------------------------------------------------
// Kernel 1: fused MLP + 60-iteration PDHG. 4 batch rows per CTA, 256 threads.
// Thread t owns primal elements n = t, t+256 (float4 across the 4 rows);
// threads t<128 own dual element m = t.
// ---------------------------------------------------------------------------
__global__ void __launch_bounds__(256) solve_kernel(
    const float* __restrict__ X,
    const float* __restrict__ W1, const float* __restrict__ B1,
    const float* __restrict__ W2, const float* __restrict__ B2,
    const float* __restrict__ W3, const float* __restrict__ B3,
    const float* __restrict__ W4, const float* __restrict__ B4,
    float* __restrict__ out)
{
    const int row0 = blockIdx.x * RROWS;
    const int t    = threadIdx.x;   // 0..255

    __shared__ float4 bx_sh[MDIM];
    __shared__ float4 xb_sh[NDIM];
    __shared__ float4 lam1_sh[MDIM];
    __shared__ float  h_sh[RROWS][HID + 4];
    __shared__ float4 red[8];

    if (t < MDIM) {
        float4 v;
        v.x = X[(row0 + 0) * MDIM + t];
        v.y = X[(row0 + 1) * MDIM + t];
        v.z = X[(row0 + 2) * MDIM + t];
        v.w = X[(row0 + 3) * MDIM + t];
        bx_sh[t] = v;
    }
    __syncthreads();

    // ---- MLP (threads 0..79 = (row r, unit i)) ----
    if (t < RROWS * HID) {
        const int r = t / HID, i = t % HID;
        float a = B1[i];
        for (int k = 0; k < MDIM; k++)
            a += ((const float*)&bx_sh[k])[r] * W1[k * HID + i];
        h_sh[r][i] = tanhf(a);
    }
    __syncthreads();
    {
        float a = 0.0f;
        if (t < RROWS * HID) {
            const int r = t / HID, i = t % HID;
            a = B2[i];
            #pragma unroll
            for (int k = 0; k < HID; k++) a += h_sh[r][k] * W2[k * HID + i];
            a = tanhf(a);
        }
        __syncthreads();
        if (t < RROWS * HID) h_sh[t / HID][t % HID] = a;
        __syncthreads();
        if (t < RROWS * HID) {
            const int r = t / HID, i = t % HID;
            a = B3[i];
            #pragma unroll
            for (int k = 0; k < HID; k++) a += h_sh[r][k] * W3[k * HID + i];
            a = tanhf(a);
        }
        __syncthreads();
        if (t < RROWS * HID) h_sh[t / HID][t % HID] = a;
        __syncthreads();
    }

    float4 z[2], x[2], lam2[2], xb[2];
    #pragma unroll
    for (int k = 0; k < 2; k++) {
        const int n = t + 256 * k;
        const float b4v = B4[n];
        float4 a = make_float4(b4v, b4v, b4v, b4v);
        #pragma unroll
        for (int j = 0; j < HID; j++) {
            const float w = W4[j * NDIM + n];
            a.x += h_sh[0][j] * w;
            a.y += h_sh[1][j] * w;
            a.z += h_sh[2][j] * w;
            a.w += h_sh[3][j] * w;
        }
        z[k] = a;
        x[k] = make_float4(fmaxf(a.x, 0.f), fmaxf(a.y, 0.f),
                           fmaxf(a.z, 0.f), fmaxf(a.w, 0.f));
        lam2[k] = make_float4(0.f, 0.f, 0.f, 0.f);
        xb[k] = x[k];
        xb_sh[n] = x[k];
    }

    const float tau = g_tau;                  // sig == tau
    float4 lam1r = make_float4(0.f, 0.f, 0.f, 0.f);
    float4 taub  = make_float4(0.f, 0.f, 0.f, 0.f);
    int rcnt = 0;
    if (t < MDIM) {
        rcnt = g_csr_cnt[t];
        const float4 b4 = bx_sh[t];
        taub = make_float4(tau * b4.x, tau * b4.y, tau * b4.z, tau * b4.w);
        lam1_sh[t] = lam1r;
    }
    const int cc0 = g_csc_cnt[t];
    const int cc1 = g_csc_cnt[t + 256];
    __syncthreads();

    // ---- PDHG mainloop ----
    for (int it = 0; it < NITER; it++) {
        // dual 1 (threads < 128): lam1 = max(lam1 + sig*(S xb) - sig*b, 0)
        if (t < MDIM) {
            float4 acc = make_float4(0.f, 0.f, 0.f, 0.f);
            for (int j = 0; j < rcnt; j++) {
                const int idx = g_csr_idxT[j * MDIM + t];   // coalesced
                acc = f4add(acc, xb_sh[idx]);               // bank-scheduled gather
            }
            lam1r.x = fmaxf(fmaf(tau, acc.x, lam1r.x) - taub.x, 0.f);
            lam1r.y = fmaxf(fmaf(tau, acc.y, lam1r.y) - taub.y, 0.f);
            lam1r.z = fmaxf(fmaf(tau, acc.z, lam1r.z) - taub.z, 0.f);
            lam1r.w = fmaxf(fmaf(tau, acc.w, lam1r.w) - taub.w, 0.f);
            lam1_sh[t] = lam1r;
        }
        // dual 2 (all threads, registers only)
        #pragma unroll
        for (int k = 0; k < 2; k++) {
            lam2[k].x = fminf(fmaf(tau, xb[k].x, lam2[k].x), 0.f);
            lam2[k].y = fminf(fmaf(tau, xb[k].y, lam2[k].y), 0.f);
            lam2[k].z = fminf(fmaf(tau, xb[k].z, lam2[k].z), 0.f);
            lam2[k].w = fminf(fmaf(tau, xb[k].w, lam2[k].w), 0.f);
        }
        __syncthreads();

        // primal: u = x - tau*(S^T lam1 + lam2) + tau - z
        float4 u[2];
        float4 ss = make_float4(0.f, 0.f, 0.f, 0.f);
        #pragma unroll
        for (int k = 0; k < 2; k++) {
            const int n = t + 256 * k;
            const int cnt = k ? cc1 : cc0;
            float4 ca = make_float4(0.f, 0.f, 0.f, 0.f);
            for (int j = 0; j < cnt; j++) {
                const int idx = g_csc_idxT[j * NDIM + n];   // coalesced
                ca = f4add(ca, lam1_sh[idx]);               // bank-scheduled gather
            }
            u[k].x = (x[k].x - tau * (ca.x + lam2[k].x)) + tau - z[k].x;
            u[k].y = (x[k].y - tau * (ca.y + lam2[k].y)) + tau - z[k].y;
            u[k].z = (x[k].z - tau * (ca.z + lam2[k].z)) + tau - z[k].z;
            u[k].w = (x[k].w - tau * (ca.w + lam2[k].w)) + tau - z[k].w;
            ss.x += u[k].x * u[k].x;
            ss.y += u[k].y * u[k].y;
            ss.z += u[k].z * u[k].z;
            ss.w += u[k].w * u[k].w;
        }

        // block reduce ||u||^2 per row over 256 threads (8 warps)
        #pragma unroll
        for (int o = 16; o > 0; o >>= 1) {
            ss.x += __shfl_xor_sync(0xffffffffu, ss.x, o);
            ss.y += __shfl_xor_sync(0xffffffffu, ss.y, o);
            ss.z += __shfl_xor_sync(0xffffffffu, ss.z, o);
            ss.w += __shfl_xor_sync(0xffffffffu, ss.w, o);
        }
        if ((t & 31) == 0) red[t >> 5] = ss;
        __syncthreads();
        {
            float4 tot = f4add(f4add(red[0], red[1]), f4add(red[2], red[3]));
            tot = f4add(tot, f4add(f4add(red[4], red[5]), f4add(red[6], red[7])));
            const float tc = tau * CONTROLF;
            float4 sc;
            sc.x = fmaxf(0.f, 1.f - tc / fmaxf(sqrtf(tot.x), 1e-12f));
            sc.y = fmaxf(0.f, 1.f - tc / fmaxf(sqrtf(tot.y), 1e-12f));
            sc.z = fmaxf(0.f, 1.f - tc / fmaxf(sqrtf(tot.z), 1e-12f));
            sc.w = fmaxf(0.f, 1.f - tc / fmaxf(sqrtf(tot.w), 1e-12f));

            #pragma unroll
            for (int k = 0; k < 2; k++) {
                float4 xn;
                xn.x = fmaf(sc.x, u[k].x, z[k].x);
                xn.y = fmaf(sc.y, u[k].y, z[k].y);
                xn.z = fmaf(sc.z, u[k].z, z[k].z);
                xn.w = fmaf(sc.w, u[k].w, z[k].w);
                float4 nb;
                nb.x = 2.f * xn.x - x[k].x;
                nb.y = 2.f * xn.y - x[k].y;
                nb.z = 2.f * xn.z - x[k].z;
                nb.w = 2.f * xn.w - x[k].w;
                x[k] = xn;
                xb[k] = nb;
                xb_sh[t + 256 * k] = nb;
            }
        }
        __syncthreads();
    }

    #pragma unroll
    for (int k = 0; k < 2; k++) {
        const int n = t + 256 * k;
        out[(row0 + 0) * NDIM + n] = x[k].x;
        out[(row0 + 1) * NDIM + n] = x[k].y;
        out[(row0 + 2) * NDIM + n] = x[k].z;
        out[(row0 + 3) * NDIM + n] = x[k].w;
    }
}

// ---------------------------------------------------------------------------
extern "C" void kernel_launch(void* const* d_in, const int* in_sizes, int n_in,
                              void* d_out, int out_size) {
    const float* X  = (const float*)d_in[0];
    const float* W1 = (const float*)d_in[1];
    const float* B1 = (const float*)d_in[2];
    const float* W2 = (const float*)d_in[3];
    const float* B2 = (const float*)d_in[4];
    const float* W3 = (const float*)d_in[5];
    const float* B3 = (const float*)d_in[6];
    const float* W4 = (const float*)d_in[7];
    const float* B4 = (const float*)d_in[8];
    const float* S  = (const float*)d_in[9];
    const int batch = in_sizes[0] / MDIM;

    prep_kernel<<<1, NDIM>>>(S);
    solve_kernel<<<batch / RROWS, 256>>>(X, W1, B1, W2, B2, W3, B3, W4, B4,
                                         (float*)d_out);
}

// round 4
// speedup vs baseline: 1.1440x; 1.1440x over previous
#include <cuda_runtime.h>
#include <math.h>

#define MDIM 128        // N_COMBOS (dual dim)
#define NDIM 512        // N_STRUCTS (primal dim)
#define HID  20
#define NITER 60
#define CONTROLF 10.0f
#define RCAP 64         // max nnz per row of S (mean ~16)
#define CCAP 24         // max nnz per col of S (mean ~4)
#define RROWS 4         // batch rows per CTA

// Scratch (no allocations allowed). idxT arrays are transposed [j][owner] so
// per-iteration index loads are coalesced across threads.
__device__ int            g_csr_cnt[MDIM];
__device__ unsigned short g_csr_idxT[RCAP * MDIM];   // [j][m]
__device__ int            g_csc_cnt[NDIM];
__device__ unsigned char  g_csc_idxT[CCAP * NDIM];   // [j][n]
__device__ float          g_tau;

// ---------------------------------------------------------------------------
// Kernel 0a: parallel structure build. Grid = 5 blocks x 128 threads.
// Blocks 0..3: CSC columns (thread-per-column, coalesced row sweeps).
// Block 4:     CSR rows via warp ballot (each warp scans rows with 32 lanes).
// ---------------------------------------------------------------------------
__global__ void build_kernel(const float* __restrict__ S) {
    const int t = threadIdx.x;       // 0..127
    const int b = blockIdx.x;

    if (b < 4) {
        const int n = b * 128 + t;   // column
        int cnt = 0;
        for (int m = 0; m < MDIM; m++) {
            if (S[m * NDIM + n] != 0.0f) {
                if (cnt < CCAP) g_csc_idxT[cnt * NDIM + n] = (unsigned char)m;
                cnt++;
            }
        }
        g_csc_cnt[n] = cnt < CCAP ? cnt : CCAP;
    } else {
        // CSR via ballot: warp w handles rows 32w..32w+31
        const int lane = t & 31;
        const int w    = t >> 5;     // 0..3
        for (int r = 0; r < 32; r++) {
            const int m = w * 32 + r;
            int c = 0;
            for (int j = 0; j < NDIM / 32; j++) {
                const int n = lane + 32 * j;
                const bool nz = (S[m * NDIM + n] != 0.0f);
                const unsigned mask = __ballot_sync(0xffffffffu, nz);
                if (nz) {
                    const int pos = c + __popc(mask & ((1u << lane) - 1u));
                    if (pos < RCAP) g_csr_idxT[pos * MDIM + m] = (unsigned short)n;
                }
                c += __popc(mask);
            }
            if (lane == 0) g_csr_cnt[m] = c < RCAP ? c : RCAP;
        }
    }
}

// ---------------------------------------------------------------------------
// Kernel 0b: 30-step power iteration for L = sqrt(lambda_max(S^T S + I));
// tau = sig = 0.9/L. One block, 512 threads.
// ---------------------------------------------------------------------------
__global__ void power_kernel() {
    const int t = threadIdx.x;  // 0..511

    __shared__ float v[NDIM];
    __shared__ float p[MDIM];
    __shared__ float red[16];

    v[t] = 1.0f;
    __syncthreads();

    const int ccnt = g_csc_cnt[t];
    float Lsq = 0.0f;

    for (int it = 0; it <= 30; it++) {
        if (t < MDIM) {
            float a = 0.0f;
            const int rc = g_csr_cnt[t];
            for (int j = 0; j < rc; j++) a += v[g_csr_idxT[j * MDIM + t]];
            p[t] = a;
        }
        __syncthreads();
        float a = v[t];
        for (int j = 0; j < ccnt; j++) a += p[g_csc_idxT[j * NDIM + t]];

        float s = (it == 30) ? (a * v[t]) : (a * a);
        #pragma unroll
        for (int o = 16; o > 0; o >>= 1) s += __shfl_xor_sync(0xffffffffu, s, o);
        if ((t & 31) == 0) red[t >> 5] = s;
        __syncthreads();
        float tot = 0.0f;
        #pragma unroll
        for (int ww = 0; ww < 16; ww++) tot += red[ww];

        if (it == 30) { Lsq = tot; break; }
        v[t] = a / sqrtf(tot);
        __syncthreads();
    }

    if (t == 0) g_tau = 0.9f / sqrtf(Lsq);
}

__device__ __forceinline__ float4 f4add(float4 a, float4 b) {
    return make_float4(a.x + b.x, a.y + b.y, a.z + b.z, a.w + b.w);
}

// ---------------------------------------------------------------------------
// Kernel 1: fused MLP + 60-iteration PDHG. 4 batch rows per CTA, 128 threads.
// Thread t owns primal elements n = t + 128k (k=0..3, float4 across 4 rows)
// and dual element m = t.
// ---------------------------------------------------------------------------
__global__ void __launch_bounds__(128) solve_kernel(
    const float* __restrict__ X,
    const float* __restrict__ W1, const float* __restrict__ B1,
    const float* __restrict__ W2, const float* __restrict__ B2,
    const float* __restrict__ W3, const float* __restrict__ B3,
    const float* __restrict__ W4, const float* __restrict__ B4,
    float* __restrict__ out)
{
    const int row0 = blockIdx.x * RROWS;
    const int t    = threadIdx.x;   // 0..127

    __shared__ float4 bx_sh[MDIM];
    __shared__ float4 xb_sh[NDIM];
    __shared__ float4 lam1_sh[MDIM];
    __shared__ float  h_sh[RROWS][HID + 4];
    __shared__ float4 red[4];

    {
        float4 v;
        v.x = X[(row0 + 0) * MDIM + t];
        v.y = X[(row0 + 1) * MDIM + t];
        v.z = X[(row0 + 2) * MDIM + t];
        v.w = X[(row0 + 3) * MDIM + t];
        bx_sh[t] = v;
    }
    __syncthreads();

    // ---- MLP (threads 0..79 = (row r, unit i)) ----
    if (t < RROWS * HID) {
        const int r = t / HID, i = t % HID;
        float a = B1[i];
        for (int k = 0; k < MDIM; k++)
            a += ((const float*)&bx_sh[k])[r] * W1[k * HID + i];
        h_sh[r][i] = tanhf(a);
    }
    __syncthreads();
    {
        float a = 0.0f;
        if (t < RROWS * HID) {
            const int r = t / HID, i = t % HID;
            a = B2[i];
            #pragma unroll
            for (int k = 0; k < HID; k++) a += h_sh[r][k] * W2[k * HID + i];
            a = tanhf(a);
        }
        __syncthreads();
        if (t < RROWS * HID) h_sh[t / HID][t % HID] = a;
        __syncthreads();
        if (t < RROWS * HID) {
            const int r = t / HID, i = t % HID;
            a = B3[i];
            #pragma unroll
            for (int k = 0; k < HID; k++) a += h_sh[r][k] * W3[k * HID + i];
            a = tanhf(a);
        }
        __syncthreads();
        if (t < RROWS * HID) h_sh[t / HID][t % HID] = a;
        __syncthreads();
    }

    float4 z[4], x[4], lam2[4], xb[4];
    #pragma unroll
    for (int k = 0; k < 4; k++) {
        const int n = t + 128 * k;
        const float b4v = B4[n];
        float4 a = make_float4(b4v, b4v, b4v, b4v);
        #pragma unroll
        for (int j = 0; j < HID; j++) {
            const float w = W4[j * NDIM + n];
            a.x += h_sh[0][j] * w;
            a.y += h_sh[1][j] * w;
            a.z += h_sh[2][j] * w;
            a.w += h_sh[3][j] * w;
        }
        z[k] = a;
        x[k] = make_float4(fmaxf(a.x, 0.f), fmaxf(a.y, 0.f),
                           fmaxf(a.z, 0.f), fmaxf(a.w, 0.f));
        lam2[k] = make_float4(0.f, 0.f, 0.f, 0.f);
        xb[k] = x[k];
        xb_sh[n] = x[k];
    }

    const float tau = g_tau;                  // sig == tau
    float4 lam1r = make_float4(0.f, 0.f, 0.f, 0.f);
    lam1_sh[t] = lam1r;
    const float4 b4 = bx_sh[t];
    const float4 taub = make_float4(tau * b4.x, tau * b4.y,
                                    tau * b4.z, tau * b4.w);
    const int rcnt = g_csr_cnt[t];
    int cc[4];
    #pragma unroll
    for (int k = 0; k < 4; k++) cc[k] = g_csc_cnt[t + 128 * k];
    __syncthreads();

    // ---- PDHG mainloop ----
    for (int it = 0; it < NITER; it++) {
        // dual 1: lam1 = max(lam1 + sig*(S xb) - sig*b, 0)
        // 2-way unrolled independent accumulators for ILP.
        {
            float4 a0 = make_float4(0.f, 0.f, 0.f, 0.f);
            float4 a1 = make_float4(0.f, 0.f, 0.f, 0.f);
            int j = 0;
            for (; j + 2 <= rcnt; j += 2) {
                const int i0 = g_csr_idxT[j * MDIM + t];
                const int i1 = g_csr_idxT[(j + 1) * MDIM + t];
                const float4 v0 = xb_sh[i0];
                const float4 v1 = xb_sh[i1];
                a0 = f4add(a0, v0);
                a1 = f4add(a1, v1);
            }
            if (j < rcnt) a0 = f4add(a0, xb_sh[g_csr_idxT[j * MDIM + t]]);
            const float4 acc = f4add(a0, a1);
            lam1r.x = fmaxf(fmaf(tau, acc.x, lam1r.x) - taub.x, 0.f);
            lam1r.y = fmaxf(fmaf(tau, acc.y, lam1r.y) - taub.y, 0.f);
            lam1r.z = fmaxf(fmaf(tau, acc.z, lam1r.z) - taub.z, 0.f);
            lam1r.w = fmaxf(fmaf(tau, acc.w, lam1r.w) - taub.w, 0.f);
            lam1_sh[t] = lam1r;
        }
        // dual 2 (registers only)
        #pragma unroll
        for (int k = 0; k < 4; k++) {
            lam2[k].x = fminf(fmaf(tau, xb[k].x, lam2[k].x), 0.f);
            lam2[k].y = fminf(fmaf(tau, xb[k].y, lam2[k].y), 0.f);
            lam2[k].z = fminf(fmaf(tau, xb[k].z, lam2[k].z), 0.f);
            lam2[k].w = fminf(fmaf(tau, xb[k].w, lam2[k].w), 0.f);
        }
        __syncthreads();

        // primal: u = x - tau*(S^T lam1 + lam2) + tau - z
        float4 u[4];
        float4 ss = make_float4(0.f, 0.f, 0.f, 0.f);
        #pragma unroll
        for (int k = 0; k < 4; k++) {
            const int n = t + 128 * k;
            const int cnt = cc[k];
            float4 c0 = make_float4(0.f, 0.f, 0.f, 0.f);
            float4 c1 = make_float4(0.f, 0.f, 0.f, 0.f);
            int j = 0;
            for (; j + 2 <= cnt; j += 2) {
                const int i0 = g_csc_idxT[j * NDIM + n];
                const int i1 = g_csc_idxT[(j + 1) * NDIM + n];
                const float4 v0 = lam1_sh[i0];
                const float4 v1 = lam1_sh[i1];
                c0 = f4add(c0, v0);
                c1 = f4add(c1, v1);
            }
            if (j < cnt) c0 = f4add(c0, lam1_sh[g_csc_idxT[j * NDIM + n]]);
            const float4 ca = f4add(c0, c1);
            u[k].x = (x[k].x - tau * (ca.x + lam2[k].x)) + tau - z[k].x;
            u[k].y = (x[k].y - tau * (ca.y + lam2[k].y)) + tau - z[k].y;
            u[k].z = (x[k].z - tau * (ca.z + lam2[k].z)) + tau - z[k].z;
            u[k].w = (x[k].w - tau * (ca.w + lam2[k].w)) + tau - z[k].w;
            ss.x += u[k].x * u[k].x;
            ss.y += u[k].y * u[k].y;
            ss.z += u[k].z * u[k].z;
            ss.w += u[k].w * u[k].w;
        }

        // block reduce ||u||^2 per row over 128 threads (4 warps)
        #pragma unroll
        for (int o = 16; o > 0; o >>= 1) {
            ss.x += __shfl_xor_sync(0xffffffffu, ss.x, o);
            ss.y += __shfl_xor_sync(0xffffffffu, ss.y, o);
            ss.z += __shfl_xor_sync(0xffffffffu, ss.z, o);
            ss.w += __shfl_xor_sync(0xffffffffu, ss.w, o);
        }
        if ((t & 31) == 0) red[t >> 5] = ss;
        __syncthreads();
        {
            const float4 tot = f4add(f4add(red[0], red[1]), f4add(red[2], red[3]));
            const float tc = tau * CONTROLF;
            float4 sc;
            sc.x = fmaxf(0.f, 1.f - tc / fmaxf(sqrtf(tot.x), 1e-12f));
            sc.y = fmaxf(0.f, 1.f - tc / fmaxf(sqrtf(tot.y), 1e-12f));
            sc.z = fmaxf(0.f, 1.f - tc / fmaxf(sqrtf(tot.z), 1e-12f));
            sc.w = fmaxf(0.f, 1.f - tc / fmaxf(sqrtf(tot.w), 1e-12f));

            #pragma unroll
            for (int k = 0; k < 4; k++) {
                float4 xn;
                xn.x = fmaf(sc.x, u[k].x, z[k].x);
                xn.y = fmaf(sc.y, u[k].y, z[k].y);
                xn.z = fmaf(sc.z, u[k].z, z[k].z);
                xn.w = fmaf(sc.w, u[k].w, z[k].w);
                float4 nb;
                nb.x = 2.f * xn.x - x[k].x;
                nb.y = 2.f * xn.y - x[k].y;
                nb.z = 2.f * xn.z - x[k].z;
                nb.w = 2.f * xn.w - x[k].w;
                x[k] = xn;
                xb[k] = nb;
                xb_sh[t + 128 * k] = nb;
            }
        }
        __syncthreads();
    }

    #pragma unroll
    for (int k = 0; k < 4; k++) {
        const int n = t + 128 * k;
        out[(row0 + 0) * NDIM + n] = x[k].x;
        out[(row0 + 1) * NDIM + n] = x[k].y;
        out[(row0 + 2) * NDIM + n] = x[k].z;
        out[(row0 + 3) * NDIM + n] = x[k].w;
    }
}

// ---------------------------------------------------------------------------
extern "C" void kernel_launch(void* const* d_in, const int* in_sizes, int n_in,
                              void* d_out, int out_size) {
    const float* X  = (const float*)d_in[0];
    const float* W1 = (const float*)d_in[1];
    const float* B1 = (const float*)d_in[2];
    const float* W2 = (const float*)d_in[3];
    const float* B2 = (const float*)d_in[4];
    const float* W3 = (const float*)d_in[5];
    const float* B3 = (const float*)d_in[6];
    const float* W4 = (const float*)d_in[7];
    const float* B4 = (const float*)d_in[8];
    const float* S  = (const float*)d_in[9];
    const int batch = in_sizes[0] / MDIM;

    build_kernel<<<5, 128>>>(S);
    power_kernel<<<1, NDIM>>>();
    solve_kernel<<<batch / RROWS, 128>>>(X, W1, B1, W2, B2, W3, B3, W4, B4,
                                         (float*)d_out);
}

// round 6
// speedup vs baseline: 1.6776x; 1.4665x over previous
#include <cuda_runtime.h>
#include <cuda_fp16.h>
#include <math.h>

#define MDIM 128        // N_COMBOS (dual dim)
#define NDIM 512        // N_STRUCTS (primal dim)
#define HID  20
#define NITER 60
#define CONTROLF 10.0f
#define RJJ  16         // max ceil(row_nnz/4)  (row nnz mean 16, cap 64)
#define CJJ  6          // max ceil(col_nnz/4)  (col nnz mean 4, cap 24)
#define RROWS 4         // batch rows per CTA

// Packed, transposed, zero-slot-padded index lists.
// csr: ushort4 g_csr_pk[jj*MDIM + m] = 4 column indices (pad = NDIM -> zero slot)
// csc: uchar4  g_csc_pk[jj*NDIM + n] = 4 row indices    (pad = MDIM -> zero slot)
__device__ int     g_csr_cnt[MDIM];              // jj counts
__device__ ushort4 g_csr_pk[RJJ * MDIM];
__device__ int     g_csc_cnt[NDIM];              // jj counts
__device__ uchar4  g_csc_pk[CJJ * NDIM];
__device__ float   g_tau;

// ---------------------------------------------------------------------------
// Kernel 0a: structure build, latency-hidden. Grid = 8 blocks x 128 threads.
// Blocks 0..3: CSC (thread-per-column, 16-deep load prefetch).
// Blocks 4..7: CSR (warp ballots, values prefetched per row).
// ---------------------------------------------------------------------------
__global__ void build_kernel(const float* __restrict__ S) {
    const int t = threadIdx.x;       // 0..127
    const int b = blockIdx.x;

    if (b < 4) {
        const int n = b * 128 + t;   // column
        unsigned char* pk = reinterpret_cast<unsigned char*>(g_csc_pk);  // BYTE writes
        int cnt = 0;
        for (int c = 0; c < MDIM; c += 16) {
            float vals[16];
            #pragma unroll
            for (int i = 0; i < 16; i++) vals[i] = S[(c + i) * NDIM + n];
            #pragma unroll
            for (int i = 0; i < 16; i++) {
                if (vals[i] != 0.0f) {
                    const int jj = cnt >> 2, r = cnt & 3;
                    if (jj < CJJ) pk[(jj * NDIM + n) * 4 + r] = (unsigned char)(c + i);
                    cnt++;
                }
            }
        }
        if (cnt > CJJ * 4) cnt = CJJ * 4;
        const int cnt4 = (cnt + 3) >> 2;
        for (int j = cnt; j < cnt4 * 4; j++)
            pk[((j >> 2) * NDIM + n) * 4 + (j & 3)] = (unsigned char)MDIM; // pad -> zero slot
        g_csc_cnt[n] = cnt4;
    } else {
        const int lane = t & 31;
        const int w    = t >> 5;
        unsigned short* pk = reinterpret_cast<unsigned short*>(g_csr_pk);
        for (int r = 0; r < 8; r++) {
            const int m = (b - 4) * 32 + w * 8 + r;
            float vals[16];
            #pragma unroll
            for (int j = 0; j < 16; j++) vals[j] = S[m * NDIM + lane + 32 * j];
            int c = 0;
            #pragma unroll
            for (int j = 0; j < 16; j++) {
                const bool nz = (vals[j] != 0.0f);
                const unsigned mask = __ballot_sync(0xffffffffu, nz);
                if (nz) {
                    const int pos = c + __popc(mask & ((1u << lane) - 1u));
                    if (pos < RJJ * 4)
                        pk[((pos >> 2) * MDIM + m) * 4 + (pos & 3)] =
                            (unsigned short)(lane + 32 * j);
                }
                c += __popc(mask);
            }
            if (c > RJJ * 4) c = RJJ * 4;
            const int cnt4 = (c + 3) >> 2;
            if (lane == 0) {
                for (int j = c; j < cnt4 * 4; j++)
                    pk[((j >> 2) * MDIM + m) * 4 + (j & 3)] = (unsigned short)NDIM;
                g_csr_cnt[m] = cnt4;
            }
        }
    }
}

// ---------------------------------------------------------------------------
// Kernel 0b: 30-step power iteration; tau = 0.9 / sqrt(lmax(S^T S + I)).
// One block, 512 threads. Uses zero slots v[NDIM], p[MDIM].
// ---------------------------------------------------------------------------
__global__ void power_kernel() {
    const int t = threadIdx.x;

    __shared__ float v[NDIM + 1];
    __shared__ float p[MDIM + 1];
    __shared__ float red[16];

    v[t] = 1.0f;
    if (t == 0) { v[NDIM] = 0.0f; p[MDIM] = 0.0f; }
    __syncthreads();

    const int ccnt = g_csc_cnt[t];
    float Lsq = 0.0f;

    for (int it = 0; it <= 30; it++) {
        if (t < MDIM) {
            float a = 0.0f;
            const int rc = g_csr_cnt[t];
            for (int jj = 0; jj < rc; jj++) {
                const ushort4 id = g_csr_pk[jj * MDIM + t];
                a += v[id.x] + v[id.y] + v[id.z] + v[id.w];
            }
            p[t] = a;
        }
        __syncthreads();
        float a = v[t];
        for (int jj = 0; jj < ccnt; jj++) {
            const uchar4 id = g_csc_pk[jj * NDIM + t];
            a += p[id.x] + p[id.y] + p[id.z] + p[id.w];
        }

        float s = (it == 30) ? (a * v[t]) : (a * a);
        #pragma unroll
        for (int o = 16; o > 0; o >>= 1) s += __shfl_xor_sync(0xffffffffu, s, o);
        if ((t & 31) == 0) red[t >> 5] = s;
        __syncthreads();
        float tot = 0.0f;
        #pragma unroll
        for (int ww = 0; ww < 16; ww++) tot += red[ww];

        if (it == 30) { Lsq = tot; break; }
        v[t] = a / sqrtf(tot);
        __syncthreads();
    }

    if (t == 0) g_tau = 0.9f / sqrtf(Lsq);
}

// ---------------------------------------------------------------------------
__device__ __forceinline__ float4 f4add(float4 a, float4 b) {
    return make_float4(a.x + b.x, a.y + b.y, a.z + b.z, a.w + b.w);
}
__device__ __forceinline__ uint2 packh4(float4 v) {
    const __half2 lo = __floats2half2_rn(v.x, v.y);
    const __half2 hi = __floats2half2_rn(v.z, v.w);
    uint2 r;
    r.x = *reinterpret_cast<const unsigned*>(&lo);
    r.y = *reinterpret_cast<const unsigned*>(&hi);
    return r;
}
__device__ __forceinline__ void acch4(float4& a, uint2 v) {
    const float2 lo = __half22float2(*reinterpret_cast<const __half2*>(&v.x));
    const float2 hi = __half22float2(*reinterpret_cast<const __half2*>(&v.y));
    a.x += lo.x; a.y += lo.y; a.z += hi.x; a.w += hi.y;
}

// ---------------------------------------------------------------------------
// Kernel 1: fused MLP + 60-iteration PDHG. 4 batch rows per CTA, 128 threads.
// Gathered arrays (xb, lam1) stored as packed 4xfp16; all state fp32 in regs.
// ---------------------------------------------------------------------------
__global__ void __launch_bounds__(128) solve_kernel(
    const float* __restrict__ X,
    const float* __restrict__ W1, const float* __restrict__ B1,
    const float* __restrict__ W2, const float* __restrict__ B2,
    const float* __restrict__ W3, const float* __restrict__ B3,
    const float* __restrict__ W4, const float* __restrict__ B4,
    float* __restrict__ out)
{
    const int row0 = blockIdx.x * RROWS;
    const int t    = threadIdx.x;   // 0..127

    __shared__ float4 bx_sh[MDIM];
    __shared__ uint2  xbH[NDIM + 1];     // packed 4xfp16, zero slot at NDIM
    __shared__ uint2  lam1H[MDIM + 1];   // packed 4xfp16, zero slot at MDIM
    __shared__ float  h_sh[RROWS][HID + 4];
    __shared__ float4 red[4];

    {
        float4 v;
        v.x = X[(row0 + 0) * MDIM + t];
        v.y = X[(row0 + 1) * MDIM + t];
        v.z = X[(row0 + 2) * MDIM + t];
        v.w = X[(row0 + 3) * MDIM + t];
        bx_sh[t] = v;
    }
    if (t == 0) {
        xbH[NDIM]   = make_uint2(0u, 0u);
        lam1H[MDIM] = make_uint2(0u, 0u);
    }
    __syncthreads();

    // ---- MLP (threads 0..79 = (row r, unit i)) ----
    if (t < RROWS * HID) {
        const int r = t / HID, i = t % HID;
        float a = B1[i];
        for (int k = 0; k < MDIM; k++)
            a += ((const float*)&bx_sh[k])[r] * W1[k * HID + i];
        h_sh[r][i] = tanhf(a);
    }
    __syncthreads();
    {
        float a = 0.0f;
        if (t < RROWS * HID) {
            const int r = t / HID, i = t % HID;
            a = B2[i];
            #pragma unroll
            for (int k = 0; k < HID; k++) a += h_sh[r][k] * W2[k * HID + i];
            a = tanhf(a);
        }
        __syncthreads();
        if (t < RROWS * HID) h_sh[t / HID][t % HID] = a;
        __syncthreads();
        if (t < RROWS * HID) {
            const int r = t / HID, i = t % HID;
            a = B3[i];
            #pragma unroll
            for (int k = 0; k < HID; k++) a += h_sh[r][k] * W3[k * HID + i];
            a = tanhf(a);
        }
        __syncthreads();
        if (t < RROWS * HID) h_sh[t / HID][t % HID] = a;
        __syncthreads();
    }

    float4 z[4], x[4], lam2[4], xb[4];
    #pragma unroll
    for (int k = 0; k < 4; k++) {
        const int n = t + 128 * k;
        const float b4v = B4[n];
        float4 a = make_float4(b4v, b4v, b4v, b4v);
        #pragma unroll
        for (int j = 0; j < HID; j++) {
            const float w = W4[j * NDIM + n];
            a.x += h_sh[0][j] * w;
            a.y += h_sh[1][j] * w;
            a.z += h_sh[2][j] * w;
            a.w += h_sh[3][j] * w;
        }
        z[k] = a;
        x[k] = make_float4(fmaxf(a.x, 0.f), fmaxf(a.y, 0.f),
                           fmaxf(a.z, 0.f), fmaxf(a.w, 0.f));
        lam2[k] = make_float4(0.f, 0.f, 0.f, 0.f);
        xb[k] = x[k];
        xbH[n] = packh4(x[k]);
    }

    const float tau = g_tau;                  // sig == tau
    float4 lam1r = make_float4(0.f, 0.f, 0.f, 0.f);
    lam1H[t] = make_uint2(0u, 0u);
    const float4 b4 = bx_sh[t];
    const float4 taub = make_float4(tau * b4.x, tau * b4.y,
                                    tau * b4.z, tau * b4.w);
    const int rcnt = g_csr_cnt[t];
    int cc[4];
    #pragma unroll
    for (int k = 0; k < 4; k++) cc[k] = g_csc_cnt[t + 128 * k];
    __syncthreads();

    // ---- PDHG mainloop ----
    for (int it = 0; it < NITER; it++) {
        // dual 1: lam1 = max(lam1 + sig*(S xb) - sig*b, 0)
        {
            float4 a0 = make_float4(0.f, 0.f, 0.f, 0.f);
            float4 a1 = make_float4(0.f, 0.f, 0.f, 0.f);
            for (int jj = 0; jj < rcnt; jj++) {
                const ushort4 id = g_csr_pk[jj * MDIM + t];   // 8B coalesced
                const uint2 v0 = xbH[id.x];
                const uint2 v1 = xbH[id.y];
                const uint2 v2 = xbH[id.z];
                const uint2 v3 = xbH[id.w];
                acch4(a0, v0); acch4(a1, v1);
                acch4(a0, v2); acch4(a1, v3);
            }
            const float4 acc = f4add(a0, a1);
            lam1r.x = fmaxf(fmaf(tau, acc.x, lam1r.x) - taub.x, 0.f);
            lam1r.y = fmaxf(fmaf(tau, acc.y, lam1r.y) - taub.y, 0.f);
            lam1r.z = fmaxf(fmaf(tau, acc.z, lam1r.z) - taub.z, 0.f);
            lam1r.w = fmaxf(fmaf(tau, acc.w, lam1r.w) - taub.w, 0.f);
            lam1H[t] = packh4(lam1r);
        }
        // dual 2 (registers only, exact fp32)
        #pragma unroll
        for (int k = 0; k < 4; k++) {
            lam2[k].x = fminf(fmaf(tau, xb[k].x, lam2[k].x), 0.f);
            lam2[k].y = fminf(fmaf(tau, xb[k].y, lam2[k].y), 0.f);
            lam2[k].z = fminf(fmaf(tau, xb[k].z, lam2[k].z), 0.f);
            lam2[k].w = fminf(fmaf(tau, xb[k].w, lam2[k].w), 0.f);
        }
        __syncthreads();

        // primal: u = x - tau*(S^T lam1 + lam2) + tau - z
        float4 u[4];
        float4 ss = make_float4(0.f, 0.f, 0.f, 0.f);
        #pragma unroll
        for (int k = 0; k < 4; k++) {
            const int n = t + 128 * k;
            const int cnt = cc[k];
            float4 c0 = make_float4(0.f, 0.f, 0.f, 0.f);
            float4 c1 = make_float4(0.f, 0.f, 0.f, 0.f);
            for (int jj = 0; jj < cnt; jj++) {
                const uchar4 id = g_csc_pk[jj * NDIM + n];    // 4B coalesced
                const uint2 v0 = lam1H[id.x];
                const uint2 v1 = lam1H[id.y];
                const uint2 v2 = lam1H[id.z];
                const uint2 v3 = lam1H[id.w];
                acch4(c0, v0); acch4(c1, v1);
                acch4(c0, v2); acch4(c1, v3);
            }
            const float4 ca = f4add(c0, c1);
            u[k].x = (x[k].x - tau * (ca.x + lam2[k].x)) + tau - z[k].x;
            u[k].y = (x[k].y - tau * (ca.y + lam2[k].y)) + tau - z[k].y;
            u[k].z = (x[k].z - tau * (ca.z + lam2[k].z)) + tau - z[k].z;
            u[k].w = (x[k].w - tau * (ca.w + lam2[k].w)) + tau - z[k].w;
            ss.x += u[k].x * u[k].x;
            ss.y += u[k].y * u[k].y;
            ss.z += u[k].z * u[k].z;
            ss.w += u[k].w * u[k].w;
        }

        // block reduce ||u||^2 per row over 128 threads (4 warps)
        #pragma unroll
        for (int o = 16; o > 0; o >>= 1) {
            ss.x += __shfl_xor_sync(0xffffffffu, ss.x, o);
            ss.y += __shfl_xor_sync(0xffffffffu, ss.y, o);
            ss.z += __shfl_xor_sync(0xffffffffu, ss.z, o);
            ss.w += __shfl_xor_sync(0xffffffffu, ss.w, o);
        }
        if ((t & 31) == 0) red[t >> 5] = ss;
        __syncthreads();
        {
            const float4 tot = f4add(f4add(red[0], red[1]), f4add(red[2], red[3]));
            const float tc = tau * CONTROLF;
            float4 sc;
            sc.x = fmaxf(0.f, 1.f - tc / fmaxf(sqrtf(tot.x), 1e-12f));
            sc.y = fmaxf(0.f, 1.f - tc / fmaxf(sqrtf(tot.y), 1e-12f));
            sc.z = fmaxf(0.f, 1.f - tc / fmaxf(sqrtf(tot.z), 1e-12f));
            sc.w = fmaxf(0.f, 1.f - tc / fmaxf(sqrtf(tot.w), 1e-12f));

            #pragma unroll
            for (int k = 0; k < 4; k++) {
                float4 xn;
                xn.x = fmaf(sc.x, u[k].x, z[k].x);
                xn.y = fmaf(sc.y, u[k].y, z[k].y);
                xn.z = fmaf(sc.z, u[k].z, z[k].z);
                xn.w = fmaf(sc.w, u[k].w, z[k].w);
                float4 nb;
                nb.x = 2.f * xn.x - x[k].x;
                nb.y = 2.f * xn.y - x[k].y;
                nb.z = 2.f * xn.z - x[k].z;
                nb.w = 2.f * xn.w - x[k].w;
                x[k] = xn;
                xb[k] = nb;
                xbH[t + 128 * k] = packh4(nb);
            }
        }
        __syncthreads();
    }

    #pragma unroll
    for (int k = 0; k < 4; k++) {
        const int n = t + 128 * k;
        out[(row0 + 0) * NDIM + n] = x[k].x;
        out[(row0 + 1) * NDIM + n] = x[k].y;
        out[(row0 + 2) * NDIM + n] = x[k].z;
        out[(row0 + 3) * NDIM + n] = x[k].w;
    }
}

// ---------------------------------------------------------------------------
extern "C" void kernel_launch(void* const* d_in, const int* in_sizes, int n_in,
                              void* d_out, int out_size) {
    const float* X  = (const float*)d_in[0];
    const float* W1 = (const float*)d_in[1];
    const float* B1 = (const float*)d_in[2];
    const float* W2 = (const float*)d_in[3];
    const float* B2 = (const float*)d_in[4];
    const float* W3 = (const float*)d_in[5];
    const float* B3 = (const float*)d_in[6];
    const float* W4 = (const float*)d_in[7];
    const float* B4 = (const float*)d_in[8];
    const float* S  = (const float*)d_in[9];
    const int batch = in_sizes[0] / MDIM;

    build_kernel<<<8, 128>>>(S);
    power_kernel<<<1, NDIM>>>();
    solve_kernel<<<batch / RROWS, 128>>>(X, W1, B1, W2, B2, W3, B3, W4, B4,
                                         (float*)d_out);
}